// round 1
// baseline (speedup 1.0000x reference)
#include <cuda_runtime.h>

#define BATCH 2
#define SEQ 2048
#define NEMBD 1024
#define NHEAD 16
#define HDIM 64
#define WINDOW 256
#define ATT_SCALE 0.125f   // 1/sqrt(64)

// Scratch (allocation-free rule: device globals)
__device__ float g_qkv[(size_t)BATCH * SEQ * 3 * NEMBD];   // [B, T, 3E]
__device__ float g_attn[(size_t)BATCH * SEQ * NEMBD];      // [B, T, E]

// ---------------------------------------------------------------------------
// SGEMM: C[M,N] = A[M,K] @ B[K,N] + bias[N]
// 128x128 tile, BK=8, 256 threads, 8x8 per thread.
// Requires M%128==0, N%128==0, K%8==0 (true for all shapes here).
// ---------------------------------------------------------------------------
__global__ __launch_bounds__(256)
void sgemm_bias_kernel(const float* __restrict__ A, const float* __restrict__ B,
                       const float* __restrict__ bias, float* __restrict__ C,
                       int M, int N, int K) {
    const int BM = 128, BN = 128, BK = 8, TM = 8, TN = 8;
    __shared__ float As[BK][BM];
    __shared__ float Bs[BK][BN];

    const int tid = threadIdx.x;
    const int m0 = blockIdx.y * BM;
    const int n0 = blockIdx.x * BN;

    const int tx = tid % (BN / TN);   // 0..15
    const int ty = tid / (BN / TN);   // 0..15

    // A load mapping: one float4 per thread per k-tile
    const int arow = tid >> 1;             // 0..127
    const int acol = (tid & 1) << 2;       // 0 or 4
    // B load mapping
    const int brow = tid >> 5;             // 0..7
    const int bcol = (tid & 31) << 2;      // 0..124

    float acc[TM][TN];
#pragma unroll
    for (int i = 0; i < TM; i++)
#pragma unroll
        for (int j = 0; j < TN; j++) acc[i][j] = 0.f;

    const float* Aptr = A + (size_t)(m0 + arow) * K + acol;
    const float* Bptr = B + (size_t)brow * N + n0 + bcol;

    for (int k0 = 0; k0 < K; k0 += BK) {
        float4 av = *(const float4*)(Aptr + k0);
        As[acol + 0][arow] = av.x;
        As[acol + 1][arow] = av.y;
        As[acol + 2][arow] = av.z;
        As[acol + 3][arow] = av.w;
        float4 bv = *(const float4*)(Bptr + (size_t)k0 * N);
        *(float4*)&Bs[brow][bcol] = bv;
        __syncthreads();

#pragma unroll
        for (int k = 0; k < BK; k++) {
            float a[TM], b[TN];
            *(float4*)&a[0] = *(float4*)&As[k][ty * TM];
            *(float4*)&a[4] = *(float4*)&As[k][ty * TM + 4];
            *(float4*)&b[0] = *(float4*)&Bs[k][tx * TN];
            *(float4*)&b[4] = *(float4*)&Bs[k][tx * TN + 4];
#pragma unroll
            for (int i = 0; i < TM; i++)
#pragma unroll
                for (int j = 0; j < TN; j++)
                    acc[i][j] += a[i] * b[j];
        }
        __syncthreads();
    }

    // epilogue with bias
#pragma unroll
    for (int i = 0; i < TM; i++) {
        float* crow = C + (size_t)(m0 + ty * TM + i) * N + n0 + tx * TN;
        const float* brow_bias = bias + n0 + tx * TN;
#pragma unroll
        for (int j4 = 0; j4 < TN; j4 += 4) {
            float4 bb = *(const float4*)(brow_bias + j4);
            float4 cv;
            cv.x = acc[i][j4 + 0] + bb.x;
            cv.y = acc[i][j4 + 1] + bb.y;
            cv.z = acc[i][j4 + 2] + bb.z;
            cv.w = acc[i][j4 + 3] + bb.w;
            *(float4*)(crow + j4) = cv;
        }
    }
}

// ---------------------------------------------------------------------------
// Sliding-window causal attention.
// qkv layout: [B, T, 3E]; q at offset 0, k at E, v at 2E; head h at h*HDIM.
// One block = 64 queries of one (b,h). 64 threads; thread t owns query qs+t.
// Masked entries (exp(-10000-m)) underflow to exactly 0 in fp32, so a
// window-only softmax is numerically identical to the reference.
// ---------------------------------------------------------------------------
__global__ __launch_bounds__(64)
void attn_kernel(const float* __restrict__ qkv, float* __restrict__ out) {
    const int b  = blockIdx.z;
    const int h  = blockIdx.y;
    const int qs = blockIdx.x * 64;
    const int tid = threadIdx.x;
    const int i = qs + tid;

    __shared__ float ks[64][64];
    __shared__ float vs[64][64];

    const size_t rowStride = 3 * NEMBD;

    // load this thread's query row into registers
    const float* qptr = qkv + ((size_t)b * SEQ + i) * rowStride + h * HDIM;
    float q[64];
#pragma unroll
    for (int d4 = 0; d4 < 16; d4++)
        *(float4*)&q[d4 * 4] = *(const float4*)(qptr + d4 * 4);

    float acc[64];
#pragma unroll
    for (int d = 0; d < 64; d++) acc[d] = 0.f;
    float m = -1e30f, l = 0.f;

    int kt0 = qs - WINDOW;
    if (kt0 < 0) kt0 = 0;

    for (int kt = kt0; kt <= qs; kt += 64) {
        // cooperative load of K,V tiles (64x64 each)
        const float* kbase = qkv + ((size_t)b * SEQ + kt) * rowStride + NEMBD + h * HDIM;
        const float* vbase = kbase + NEMBD;
#pragma unroll
        for (int t = 0; t < 16; t++) {
            int idx4 = tid + t * 64;            // 0..1023 (float4 index)
            int r = idx4 >> 4;
            int c = (idx4 & 15) << 2;
            *(float4*)&ks[r][c] = *(const float4*)(kbase + (size_t)r * rowStride + c);
            *(float4*)&vs[r][c] = *(const float4*)(vbase + (size_t)r * rowStride + c);
        }
        __syncthreads();

        for (int j = 0; j < 64; j++) {
            const int jg = kt + j;
            float s = 0.f;
#pragma unroll
            for (int d = 0; d < 64; d++) s += q[d] * ks[j][d];
            s *= ATT_SCALE;
            s = fminf(fmaxf(s, -10000.f), 10000.f);
            const bool valid = (jg <= i) && (jg > i - WINDOW);
            if (valid) {
                if (s > m) {
                    const float corr = __expf(m - s);
                    l *= corr;
#pragma unroll
                    for (int d = 0; d < 64; d++) acc[d] *= corr;
                    m = s;
                }
                const float p = __expf(s - m);
                l += p;
#pragma unroll
                for (int d = 0; d < 64; d++) acc[d] += p * vs[j][d];
            }
        }
        __syncthreads();
    }

    const float inv = 1.f / l;
    float* optr = out + ((size_t)b * SEQ + i) * NEMBD + h * HDIM;
#pragma unroll
    for (int d4 = 0; d4 < 16; d4++) {
        float4 v4;
        v4.x = acc[d4 * 4 + 0] * inv;
        v4.y = acc[d4 * 4 + 1] * inv;
        v4.z = acc[d4 * 4 + 2] * inv;
        v4.w = acc[d4 * 4 + 3] * inv;
        *(float4*)(optr + d4 * 4) = v4;
    }
}

// ---------------------------------------------------------------------------
extern "C" void kernel_launch(void* const* d_in, const int* in_sizes, int n_in,
                              void* d_out, int out_size) {
    const float* hidden = (const float*)d_in[0];  // [B, T, E]
    const float* w_attn = (const float*)d_in[1];  // [E, 3E]
    const float* b_attn = (const float*)d_in[2];  // [3E]
    const float* w_proj = (const float*)d_in[3];  // [E, E]
    const float* b_proj = (const float*)d_in[4];  // [E]
    float* out = (float*)d_out;

    float* qkv;  cudaGetSymbolAddress((void**)&qkv,  g_qkv);
    float* attn; cudaGetSymbolAddress((void**)&attn, g_attn);

    const int M = BATCH * SEQ;       // 4096
    const int E = NEMBD;             // 1024

    // 1) QKV projection: [4096,1024] @ [1024,3072] + b
    {
        dim3 grid(3 * E / 128, M / 128);
        sgemm_bias_kernel<<<grid, 256>>>(hidden, w_attn, b_attn, qkv, M, 3 * E, E);
    }
    // 2) windowed attention
    {
        dim3 grid(SEQ / 64, NHEAD, BATCH);
        attn_kernel<<<grid, 64>>>(qkv, attn);
    }
    // 3) output projection: [4096,1024] @ [1024,1024] + b
    {
        dim3 grid(E / 128, M / 128);
        sgemm_bias_kernel<<<grid, 256>>>(attn, w_proj, b_proj, out, M, E, E);
    }
}

// round 3
// speedup vs baseline: 1.5296x; 1.5296x over previous
#include <cuda_runtime.h>
#include <cuda_bf16.h>
#include <cstdint>

#define BATCH 2
#define SEQ 2048
#define NEMBD 1024
#define NHEAD 16
#define HDIM 64
#define WINDOW 256
#define ATT_SCALE 0.125f   // 1/sqrt(64)

// Scratch (allocation-free rule: device globals)
__device__ float g_qkv[(size_t)BATCH * SEQ * 3 * NEMBD];   // [B, T, 3E]
__device__ float g_attn[(size_t)BATCH * SEQ * NEMBD];      // [B, T, E]

// ===========================================================================
// Split fp32 -> bf16 hi + bf16 lo (residual). Missing lo*lo term ~2^-18.
// ===========================================================================
__device__ __forceinline__ void split4(float4 v, uint2& hi, uint2& lo) {
    __nv_bfloat162 h01 = __floats2bfloat162_rn(v.x, v.y);
    __nv_bfloat162 h23 = __floats2bfloat162_rn(v.z, v.w);
    float l0 = v.x - __low2float(h01), l1 = v.y - __high2float(h01);
    float l2 = v.z - __low2float(h23), l3 = v.w - __high2float(h23);
    __nv_bfloat162 lo01 = __floats2bfloat162_rn(l0, l1);
    __nv_bfloat162 lo23 = __floats2bfloat162_rn(l2, l3);
    hi.x = *(uint32_t*)&h01; hi.y = *(uint32_t*)&h23;
    lo.x = *(uint32_t*)&lo01; lo.y = *(uint32_t*)&lo23;
}

__device__ __forceinline__ void mma16816(float* c, const uint32_t* a, const uint32_t* b) {
    asm volatile(
        "mma.sync.aligned.m16n8k16.row.col.f32.bf16.bf16.f32 "
        "{%0,%1,%2,%3},{%4,%5,%6,%7},{%8,%9},{%0,%1,%2,%3};"
        : "+f"(c[0]), "+f"(c[1]), "+f"(c[2]), "+f"(c[3])
        : "r"(a[0]), "r"(a[1]), "r"(a[2]), "r"(a[3]), "r"(b[0]), "r"(b[1]));
}

// ===========================================================================
// bf16 split-precision GEMM via mma.sync: C = A@B + bias
// CTA 128x128, BK=32, 8 warps (2m x 4n), warp tile 64x32.
// SMEM rows padded to 80B -> conflict-free fragment loads.
// ===========================================================================
#define ROWB     80                        // padded row bytes (32 bf16 = 64B + 16B pad)
#define BUFB     (128 * ROWB)              // 10240 per buffer
#define STAGEB   (4 * BUFB)                // Ah, Al, Bh, Bl = 40960
#define G_SMEM   (2 * STAGEB)              // 81920

__global__ __launch_bounds__(256)
void gemm_mma_kernel(const float* __restrict__ A, const float* __restrict__ B,
                     const float* __restrict__ bias, float* __restrict__ C,
                     int M, int N, int K) {
    extern __shared__ char sm[];
    const int tid = threadIdx.x, lane = tid & 31, wid = tid >> 5;
    const int m0 = blockIdx.y * 128, n0 = blockIdx.x * 128;
    const int wm = wid >> 2, wn = wid & 3;       // warp grid 2 x 4
    const int g = lane >> 2, tig = lane & 3;

    float acc[4][4][4];
#pragma unroll
    for (int i = 0; i < 4; i++)
#pragma unroll
        for (int j = 0; j < 4; j++)
#pragma unroll
            for (int r = 0; r < 4; r++) acc[i][j][r] = 0.f;

    // per-thread global load coords
    const int a_r[4]  = { (tid + 0) >> 3, (tid + 256) >> 3, (tid + 512) >> 3, (tid + 768) >> 3 };
    const int a_c4    = tid & 7;                 // same for all 4 iters (stride 256 keeps low 3 bits)
    const int nb = (tid & 31) * 4, kb = (tid >> 5) * 4;

    float4 pa[4], pb[4];
    const int NT = K / 32;

    // ---- prefetch tile 0 ----
    {
        const float* Ag = A + (size_t)m0 * K;
#pragma unroll
        for (int i = 0; i < 4; i++)
            pa[i] = *(const float4*)(Ag + (size_t)a_r[i] * K + a_c4 * 4);
        const float* Bg = B + n0;
#pragma unroll
        for (int i = 0; i < 4; i++)
            pb[i] = *(const float4*)(Bg + (size_t)(kb + i) * N + nb);
    }

    for (int t = 0; t < NT; t++) {
        const int s = t & 1;
        // ---- store prefetched tile into stage s ----
        {
            char* ah = sm + s * STAGEB;
            char* al = ah + BUFB;
            char* bh = ah + 2 * BUFB;
            char* bl = ah + 3 * BUFB;
#pragma unroll
            for (int i = 0; i < 4; i++) {
                uint2 hv, lv; split4(pa[i], hv, lv);
                *(uint2*)(ah + a_r[i] * ROWB + a_c4 * 8) = hv;
                *(uint2*)(al + a_r[i] * ROWB + a_c4 * 8) = lv;
            }
#pragma unroll
            for (int n = 0; n < 4; n++) {
                float4 kv = make_float4(((float*)&pb[0])[n], ((float*)&pb[1])[n],
                                        ((float*)&pb[2])[n], ((float*)&pb[3])[n]);
                uint2 hv, lv; split4(kv, hv, lv);
                *(uint2*)(bh + (nb + n) * ROWB + kb * 2) = hv;
                *(uint2*)(bl + (nb + n) * ROWB + kb * 2) = lv;
            }
        }
        __syncthreads();

        // ---- issue global prefetch for t+1 ----
        if (t + 1 < NT) {
            const float* Ag = A + (size_t)m0 * K + (t + 1) * 32;
#pragma unroll
            for (int i = 0; i < 4; i++)
                pa[i] = *(const float4*)(Ag + (size_t)a_r[i] * K + a_c4 * 4);
            const float* Bg = B + (size_t)((t + 1) * 32) * N + n0;
#pragma unroll
            for (int i = 0; i < 4; i++)
                pb[i] = *(const float4*)(Bg + (size_t)(kb + i) * N + nb);
        }

        // ---- compute stage s ----
        {
            const char* ah = sm + s * STAGEB;
            const char* al = ah + BUFB;
            const char* bh = ah + 2 * BUFB;
            const char* bl = ah + 3 * BUFB;
            const int arow0 = wm * 64;
            const int nrow0 = wn * 32;

#pragma unroll
            for (int ks = 0; ks < 2; ks++) {
                const int kB = ks * 32;     // 16 bf16 = 32 bytes
                uint32_t afh[4][4], bfh[4][2], afl[4][4], bfl[4][2];

#pragma unroll
                for (int mt = 0; mt < 4; mt++)
#pragma unroll
                    for (int r = 0; r < 4; r++) {
                        int row = arow0 + mt * 16 + g + 8 * (r & 1);
                        int off = row * ROWB + kB + tig * 4 + (r >> 1) * 16;
                        afh[mt][r] = *(const uint32_t*)(ah + off);
                    }
#pragma unroll
                for (int nt = 0; nt < 4; nt++)
#pragma unroll
                    for (int r = 0; r < 2; r++) {
                        int nrow = nrow0 + nt * 8 + g;
                        int off = nrow * ROWB + kB + tig * 4 + r * 16;
                        bfh[nt][r] = *(const uint32_t*)(bh + off);
                    }
                // pass 1: Ah * Bh
#pragma unroll
                for (int mt = 0; mt < 4; mt++)
#pragma unroll
                    for (int nt = 0; nt < 4; nt++)
                        mma16816(acc[mt][nt], afh[mt], bfh[nt]);

#pragma unroll
                for (int nt = 0; nt < 4; nt++)
#pragma unroll
                    for (int r = 0; r < 2; r++) {
                        int nrow = nrow0 + nt * 8 + g;
                        int off = nrow * ROWB + kB + tig * 4 + r * 16;
                        bfl[nt][r] = *(const uint32_t*)(bl + off);
                    }
                // pass 2: Ah * Bl
#pragma unroll
                for (int mt = 0; mt < 4; mt++)
#pragma unroll
                    for (int nt = 0; nt < 4; nt++)
                        mma16816(acc[mt][nt], afh[mt], bfl[nt]);

#pragma unroll
                for (int mt = 0; mt < 4; mt++)
#pragma unroll
                    for (int r = 0; r < 4; r++) {
                        int row = arow0 + mt * 16 + g + 8 * (r & 1);
                        int off = row * ROWB + kB + tig * 4 + (r >> 1) * 16;
                        afl[mt][r] = *(const uint32_t*)(al + off);
                    }
                // pass 3: Al * Bh
#pragma unroll
                for (int mt = 0; mt < 4; mt++)
#pragma unroll
                    for (int nt = 0; nt < 4; nt++)
                        mma16816(acc[mt][nt], afl[mt], bfh[nt]);
            }
        }
        __syncthreads();
    }

    // ---- epilogue: fragments -> C with bias ----
#pragma unroll
    for (int mt = 0; mt < 4; mt++) {
#pragma unroll
        for (int nt = 0; nt < 4; nt++) {
            int row0 = m0 + wm * 64 + mt * 16 + g;
            int col  = n0 + wn * 32 + nt * 8 + tig * 2;
            float2 bb = *(const float2*)(bias + col);
            float2 v0 = make_float2(acc[mt][nt][0] + bb.x, acc[mt][nt][1] + bb.y);
            float2 v1 = make_float2(acc[mt][nt][2] + bb.x, acc[mt][nt][3] + bb.y);
            *(float2*)(C + (size_t)row0 * N + col)       = v0;
            *(float2*)(C + (size_t)(row0 + 8) * N + col) = v1;
        }
    }
}

// ---------------------------------------------------------------------------
// Sliding-window causal attention (unchanged from R1 — known correct).
// ---------------------------------------------------------------------------
__global__ __launch_bounds__(64)
void attn_kernel(const float* __restrict__ qkv, float* __restrict__ out) {
    const int b  = blockIdx.z;
    const int h  = blockIdx.y;
    const int qs = blockIdx.x * 64;
    const int tid = threadIdx.x;
    const int i = qs + tid;

    __shared__ float ks[64][64];
    __shared__ float vs[64][64];

    const size_t rowStride = 3 * NEMBD;

    const float* qptr = qkv + ((size_t)b * SEQ + i) * rowStride + h * HDIM;
    float q[64];
#pragma unroll
    for (int d4 = 0; d4 < 16; d4++)
        *(float4*)&q[d4 * 4] = *(const float4*)(qptr + d4 * 4);

    float acc[64];
#pragma unroll
    for (int d = 0; d < 64; d++) acc[d] = 0.f;
    float m = -1e30f, l = 0.f;

    int kt0 = qs - WINDOW;
    if (kt0 < 0) kt0 = 0;

    for (int kt = kt0; kt <= qs; kt += 64) {
        const float* kbase = qkv + ((size_t)b * SEQ + kt) * rowStride + NEMBD + h * HDIM;
        const float* vbase = kbase + NEMBD;
#pragma unroll
        for (int t = 0; t < 16; t++) {
            int idx4 = tid + t * 64;
            int r = idx4 >> 4;
            int c = (idx4 & 15) << 2;
            *(float4*)&ks[r][c] = *(const float4*)(kbase + (size_t)r * rowStride + c);
            *(float4*)&vs[r][c] = *(const float4*)(vbase + (size_t)r * rowStride + c);
        }
        __syncthreads();

        for (int j = 0; j < 64; j++) {
            const int jg = kt + j;
            float s = 0.f;
#pragma unroll
            for (int d = 0; d < 64; d++) s += q[d] * ks[j][d];
            s *= ATT_SCALE;
            s = fminf(fmaxf(s, -10000.f), 10000.f);
            const bool valid = (jg <= i) && (jg > i - WINDOW);
            if (valid) {
                if (s > m) {
                    const float corr = __expf(m - s);
                    l *= corr;
#pragma unroll
                    for (int d = 0; d < 64; d++) acc[d] *= corr;
                    m = s;
                }
                const float p = __expf(s - m);
                l += p;
#pragma unroll
                for (int d = 0; d < 64; d++) acc[d] += p * vs[j][d];
            }
        }
        __syncthreads();
    }

    const float inv = 1.f / l;
    float* optr = out + ((size_t)b * SEQ + i) * NEMBD + h * HDIM;
#pragma unroll
    for (int d4 = 0; d4 < 16; d4++) {
        float4 v4;
        v4.x = acc[d4 * 4 + 0] * inv;
        v4.y = acc[d4 * 4 + 1] * inv;
        v4.z = acc[d4 * 4 + 2] * inv;
        v4.w = acc[d4 * 4 + 3] * inv;
        *(float4*)(optr + d4 * 4) = v4;
    }
}

// ---------------------------------------------------------------------------
extern "C" void kernel_launch(void* const* d_in, const int* in_sizes, int n_in,
                              void* d_out, int out_size) {
    const float* hidden = (const float*)d_in[0];  // [B, T, E]
    const float* w_attn = (const float*)d_in[1];  // [E, 3E]
    const float* b_attn = (const float*)d_in[2];  // [3E]
    const float* w_proj = (const float*)d_in[3];  // [E, E]
    const float* b_proj = (const float*)d_in[4];  // [E]
    float* out = (float*)d_out;

    float* qkv;  cudaGetSymbolAddress((void**)&qkv,  g_qkv);
    float* attn; cudaGetSymbolAddress((void**)&attn, g_attn);

    const int M = BATCH * SEQ;       // 4096
    const int E = NEMBD;             // 1024

    cudaFuncSetAttribute(gemm_mma_kernel,
                         cudaFuncAttributeMaxDynamicSharedMemorySize, G_SMEM);

    // 1) QKV projection: [4096,1024] @ [1024,3072] + b
    {
        dim3 grid(3 * E / 128, M / 128);
        gemm_mma_kernel<<<grid, 256, G_SMEM>>>(hidden, w_attn, b_attn, qkv, M, 3 * E, E);
    }
    // 2) windowed attention
    {
        dim3 grid(SEQ / 64, NHEAD, BATCH);
        attn_kernel<<<grid, 64>>>(qkv, attn);
    }
    // 3) output projection: [4096,1024] @ [1024,1024] + b
    {
        dim3 grid(E / 128, M / 128);
        gemm_mma_kernel<<<grid, 256, G_SMEM>>>(attn, w_proj, b_proj, out, M, E, E);
    }
}

// round 4
// speedup vs baseline: 1.5302x; 1.0004x over previous
#include <cuda_runtime.h>
#include <cuda_bf16.h>
#include <cstdint>

#define BATCH 2
#define SEQ 2048
#define NEMBD 1024
#define NHEAD 16
#define HDIM 64
#define WINDOW 256
#define ATT_SCALE 0.125f   // 1/sqrt(64)

// Scratch (allocation-free rule: device globals)
__device__ float g_qkv[(size_t)BATCH * SEQ * 3 * NEMBD];   // [B, T, 3E]
__device__ float g_attn[(size_t)BATCH * SEQ * NEMBD];      // [B, T, E]

// ===========================================================================
// Split fp32 -> bf16 hi + bf16 lo (residual). Missing lo*lo term ~2^-18.
// ===========================================================================
__device__ __forceinline__ void split4(float4 v, uint2& hi, uint2& lo) {
    __nv_bfloat162 h01 = __floats2bfloat162_rn(v.x, v.y);
    __nv_bfloat162 h23 = __floats2bfloat162_rn(v.z, v.w);
    float l0 = v.x - __low2float(h01), l1 = v.y - __high2float(h01);
    float l2 = v.z - __low2float(h23), l3 = v.w - __high2float(h23);
    __nv_bfloat162 lo01 = __floats2bfloat162_rn(l0, l1);
    __nv_bfloat162 lo23 = __floats2bfloat162_rn(l2, l3);
    hi.x = *(uint32_t*)&h01; hi.y = *(uint32_t*)&h23;
    lo.x = *(uint32_t*)&lo01; lo.y = *(uint32_t*)&lo23;
}

__device__ __forceinline__ void mma16816(float* c, const uint32_t* a, const uint32_t* b) {
    asm volatile(
        "mma.sync.aligned.m16n8k16.row.col.f32.bf16.bf16.f32 "
        "{%0,%1,%2,%3},{%4,%5,%6,%7},{%8,%9},{%0,%1,%2,%3};"
        : "+f"(c[0]), "+f"(c[1]), "+f"(c[2]), "+f"(c[3])
        : "r"(a[0]), "r"(a[1]), "r"(a[2]), "r"(a[3]), "r"(b[0]), "r"(b[1]));
}

// ===========================================================================
// bf16 split-precision GEMM via mma.sync: C = A@B + bias
// CTA 128x128, BK=32, 8 warps (2m x 4n), warp tile 64x32.
// SMEM rows padded to 80B -> conflict-free fragment loads.
// ===========================================================================
#define ROWB     80                        // padded row bytes (32 bf16 = 64B + 16B pad)
#define BUFB     (128 * ROWB)              // 10240 per buffer
#define STAGEB   (4 * BUFB)                // Ah, Al, Bh, Bl = 40960
#define G_SMEM   (2 * STAGEB)              // 81920

__global__ __launch_bounds__(256)
void gemm_mma_kernel(const float* __restrict__ A, const float* __restrict__ B,
                     const float* __restrict__ bias, float* __restrict__ C,
                     int M, int N, int K) {
    extern __shared__ char sm[];
    const int tid = threadIdx.x, lane = tid & 31, wid = tid >> 5;
    const int m0 = blockIdx.y * 128, n0 = blockIdx.x * 128;
    const int wm = wid >> 2, wn = wid & 3;       // warp grid 2 x 4
    const int g = lane >> 2, tig = lane & 3;

    float acc[4][4][4];
#pragma unroll
    for (int i = 0; i < 4; i++)
#pragma unroll
        for (int j = 0; j < 4; j++)
#pragma unroll
            for (int r = 0; r < 4; r++) acc[i][j][r] = 0.f;

    // per-thread global load coords
    const int a_r[4]  = { (tid + 0) >> 3, (tid + 256) >> 3, (tid + 512) >> 3, (tid + 768) >> 3 };
    const int a_c4    = tid & 7;                 // same for all 4 iters (stride 256 keeps low 3 bits)
    const int nb = (tid & 31) * 4, kb = (tid >> 5) * 4;

    float4 pa[4], pb[4];
    const int NT = K / 32;

    // ---- prefetch tile 0 ----
    {
        const float* Ag = A + (size_t)m0 * K;
#pragma unroll
        for (int i = 0; i < 4; i++)
            pa[i] = *(const float4*)(Ag + (size_t)a_r[i] * K + a_c4 * 4);
        const float* Bg = B + n0;
#pragma unroll
        for (int i = 0; i < 4; i++)
            pb[i] = *(const float4*)(Bg + (size_t)(kb + i) * N + nb);
    }

    for (int t = 0; t < NT; t++) {
        const int s = t & 1;
        // ---- store prefetched tile into stage s ----
        {
            char* ah = sm + s * STAGEB;
            char* al = ah + BUFB;
            char* bh = ah + 2 * BUFB;
            char* bl = ah + 3 * BUFB;
#pragma unroll
            for (int i = 0; i < 4; i++) {
                uint2 hv, lv; split4(pa[i], hv, lv);
                *(uint2*)(ah + a_r[i] * ROWB + a_c4 * 8) = hv;
                *(uint2*)(al + a_r[i] * ROWB + a_c4 * 8) = lv;
            }
#pragma unroll
            for (int n = 0; n < 4; n++) {
                float4 kv = make_float4(((float*)&pb[0])[n], ((float*)&pb[1])[n],
                                        ((float*)&pb[2])[n], ((float*)&pb[3])[n]);
                uint2 hv, lv; split4(kv, hv, lv);
                *(uint2*)(bh + (nb + n) * ROWB + kb * 2) = hv;
                *(uint2*)(bl + (nb + n) * ROWB + kb * 2) = lv;
            }
        }
        __syncthreads();

        // ---- issue global prefetch for t+1 ----
        if (t + 1 < NT) {
            const float* Ag = A + (size_t)m0 * K + (t + 1) * 32;
#pragma unroll
            for (int i = 0; i < 4; i++)
                pa[i] = *(const float4*)(Ag + (size_t)a_r[i] * K + a_c4 * 4);
            const float* Bg = B + (size_t)((t + 1) * 32) * N + n0;
#pragma unroll
            for (int i = 0; i < 4; i++)
                pb[i] = *(const float4*)(Bg + (size_t)(kb + i) * N + nb);
        }

        // ---- compute stage s ----
        {
            const char* ah = sm + s * STAGEB;
            const char* al = ah + BUFB;
            const char* bh = ah + 2 * BUFB;
            const char* bl = ah + 3 * BUFB;
            const int arow0 = wm * 64;
            const int nrow0 = wn * 32;

#pragma unroll
            for (int ks = 0; ks < 2; ks++) {
                const int kB = ks * 32;     // 16 bf16 = 32 bytes
                uint32_t afh[4][4], bfh[4][2], afl[4][4], bfl[4][2];

#pragma unroll
                for (int mt = 0; mt < 4; mt++)
#pragma unroll
                    for (int r = 0; r < 4; r++) {
                        int row = arow0 + mt * 16 + g + 8 * (r & 1);
                        int off = row * ROWB + kB + tig * 4 + (r >> 1) * 16;
                        afh[mt][r] = *(const uint32_t*)(ah + off);
                    }
#pragma unroll
                for (int nt = 0; nt < 4; nt++)
#pragma unroll
                    for (int r = 0; r < 2; r++) {
                        int nrow = nrow0 + nt * 8 + g;
                        int off = nrow * ROWB + kB + tig * 4 + r * 16;
                        bfh[nt][r] = *(const uint32_t*)(bh + off);
                    }
                // pass 1: Ah * Bh
#pragma unroll
                for (int mt = 0; mt < 4; mt++)
#pragma unroll
                    for (int nt = 0; nt < 4; nt++)
                        mma16816(acc[mt][nt], afh[mt], bfh[nt]);

#pragma unroll
                for (int nt = 0; nt < 4; nt++)
#pragma unroll
                    for (int r = 0; r < 2; r++) {
                        int nrow = nrow0 + nt * 8 + g;
                        int off = nrow * ROWB + kB + tig * 4 + r * 16;
                        bfl[nt][r] = *(const uint32_t*)(bl + off);
                    }
                // pass 2: Ah * Bl
#pragma unroll
                for (int mt = 0; mt < 4; mt++)
#pragma unroll
                    for (int nt = 0; nt < 4; nt++)
                        mma16816(acc[mt][nt], afh[mt], bfl[nt]);

#pragma unroll
                for (int mt = 0; mt < 4; mt++)
#pragma unroll
                    for (int r = 0; r < 4; r++) {
                        int row = arow0 + mt * 16 + g + 8 * (r & 1);
                        int off = row * ROWB + kB + tig * 4 + (r >> 1) * 16;
                        afl[mt][r] = *(const uint32_t*)(al + off);
                    }
                // pass 3: Al * Bh
#pragma unroll
                for (int mt = 0; mt < 4; mt++)
#pragma unroll
                    for (int nt = 0; nt < 4; nt++)
                        mma16816(acc[mt][nt], afl[mt], bfh[nt]);
            }
        }
        __syncthreads();
    }

    // ---- epilogue: fragments -> C with bias ----
#pragma unroll
    for (int mt = 0; mt < 4; mt++) {
#pragma unroll
        for (int nt = 0; nt < 4; nt++) {
            int row0 = m0 + wm * 64 + mt * 16 + g;
            int col  = n0 + wn * 32 + nt * 8 + tig * 2;
            float2 bb = *(const float2*)(bias + col);
            float2 v0 = make_float2(acc[mt][nt][0] + bb.x, acc[mt][nt][1] + bb.y);
            float2 v1 = make_float2(acc[mt][nt][2] + bb.x, acc[mt][nt][3] + bb.y);
            *(float2*)(C + (size_t)row0 * N + col)       = v0;
            *(float2*)(C + (size_t)(row0 + 8) * N + col) = v1;
        }
    }
}

// ---------------------------------------------------------------------------
// Sliding-window causal attention (unchanged from R1 — known correct).
// ---------------------------------------------------------------------------
__global__ __launch_bounds__(64)
void attn_kernel(const float* __restrict__ qkv, float* __restrict__ out) {
    const int b  = blockIdx.z;
    const int h  = blockIdx.y;
    const int qs = blockIdx.x * 64;
    const int tid = threadIdx.x;
    const int i = qs + tid;

    __shared__ float ks[64][64];
    __shared__ float vs[64][64];

    const size_t rowStride = 3 * NEMBD;

    const float* qptr = qkv + ((size_t)b * SEQ + i) * rowStride + h * HDIM;
    float q[64];
#pragma unroll
    for (int d4 = 0; d4 < 16; d4++)
        *(float4*)&q[d4 * 4] = *(const float4*)(qptr + d4 * 4);

    float acc[64];
#pragma unroll
    for (int d = 0; d < 64; d++) acc[d] = 0.f;
    float m = -1e30f, l = 0.f;

    int kt0 = qs - WINDOW;
    if (kt0 < 0) kt0 = 0;

    for (int kt = kt0; kt <= qs; kt += 64) {
        const float* kbase = qkv + ((size_t)b * SEQ + kt) * rowStride + NEMBD + h * HDIM;
        const float* vbase = kbase + NEMBD;
#pragma unroll
        for (int t = 0; t < 16; t++) {
            int idx4 = tid + t * 64;
            int r = idx4 >> 4;
            int c = (idx4 & 15) << 2;
            *(float4*)&ks[r][c] = *(const float4*)(kbase + (size_t)r * rowStride + c);
            *(float4*)&vs[r][c] = *(const float4*)(vbase + (size_t)r * rowStride + c);
        }
        __syncthreads();

        for (int j = 0; j < 64; j++) {
            const int jg = kt + j;
            float s = 0.f;
#pragma unroll
            for (int d = 0; d < 64; d++) s += q[d] * ks[j][d];
            s *= ATT_SCALE;
            s = fminf(fmaxf(s, -10000.f), 10000.f);
            const bool valid = (jg <= i) && (jg > i - WINDOW);
            if (valid) {
                if (s > m) {
                    const float corr = __expf(m - s);
                    l *= corr;
#pragma unroll
                    for (int d = 0; d < 64; d++) acc[d] *= corr;
                    m = s;
                }
                const float p = __expf(s - m);
                l += p;
#pragma unroll
                for (int d = 0; d < 64; d++) acc[d] += p * vs[j][d];
            }
        }
        __syncthreads();
    }

    const float inv = 1.f / l;
    float* optr = out + ((size_t)b * SEQ + i) * NEMBD + h * HDIM;
#pragma unroll
    for (int d4 = 0; d4 < 16; d4++) {
        float4 v4;
        v4.x = acc[d4 * 4 + 0] * inv;
        v4.y = acc[d4 * 4 + 1] * inv;
        v4.z = acc[d4 * 4 + 2] * inv;
        v4.w = acc[d4 * 4 + 3] * inv;
        *(float4*)(optr + d4 * 4) = v4;
    }
}

// ---------------------------------------------------------------------------
extern "C" void kernel_launch(void* const* d_in, const int* in_sizes, int n_in,
                              void* d_out, int out_size) {
    const float* hidden = (const float*)d_in[0];  // [B, T, E]
    const float* w_attn = (const float*)d_in[1];  // [E, 3E]
    const float* b_attn = (const float*)d_in[2];  // [3E]
    const float* w_proj = (const float*)d_in[3];  // [E, E]
    const float* b_proj = (const float*)d_in[4];  // [E]
    float* out = (float*)d_out;

    float* qkv;  cudaGetSymbolAddress((void**)&qkv,  g_qkv);
    float* attn; cudaGetSymbolAddress((void**)&attn, g_attn);

    const int M = BATCH * SEQ;       // 4096
    const int E = NEMBD;             // 1024

    cudaFuncSetAttribute(gemm_mma_kernel,
                         cudaFuncAttributeMaxDynamicSharedMemorySize, G_SMEM);

    // 1) QKV projection: [4096,1024] @ [1024,3072] + b
    {
        dim3 grid(3 * E / 128, M / 128);
        gemm_mma_kernel<<<grid, 256, G_SMEM>>>(hidden, w_attn, b_attn, qkv, M, 3 * E, E);
    }
    // 2) windowed attention
    {
        dim3 grid(SEQ / 64, NHEAD, BATCH);
        attn_kernel<<<grid, 64>>>(qkv, attn);
    }
    // 3) output projection: [4096,1024] @ [1024,1024] + b
    {
        dim3 grid(E / 128, M / 128);
        gemm_mma_kernel<<<grid, 256, G_SMEM>>>(attn, w_proj, b_proj, out, M, E, E);
    }
}

// round 5
// speedup vs baseline: 1.9431x; 1.2698x over previous
#include <cuda_runtime.h>
#include <cuda_bf16.h>
#include <cstdint>

#define BATCH 2
#define SEQ 2048
#define NEMBD 1024
#define NHEAD 16
#define HDIM 64
#define WINDOW 256
#define ATT_SCALE 0.125f   // 1/sqrt(64)

typedef unsigned long long ull;

// ---------------- device scratch (allocation-free rule) ----------------
__device__ float g_qkv[(size_t)BATCH * SEQ * 3 * NEMBD];       // [4096, 3072] fp32
__device__ __nv_bfloat16 g_ah[(size_t)4096 * 1024];            // hidden hi
__device__ __nv_bfloat16 g_al[(size_t)4096 * 1024];            // hidden lo
__device__ __nv_bfloat16 g_wh[(size_t)3072 * 1024];            // w_attn^T hi [N][K]
__device__ __nv_bfloat16 g_wl[(size_t)3072 * 1024];
__device__ __nv_bfloat16 g_ph[(size_t)1024 * 1024];            // w_proj^T hi
__device__ __nv_bfloat16 g_pl[(size_t)1024 * 1024];
__device__ __nv_bfloat16 g_oh[(size_t)4096 * 1024];            // attn out hi
__device__ __nv_bfloat16 g_ol[(size_t)4096 * 1024];

// ---------------- small helpers ----------------
__device__ __forceinline__ uint32_t smem_u32(const void* p) {
    uint32_t a;
    asm("{ .reg .u64 t; cvta.to.shared.u64 t, %1; cvt.u32.u64 %0, t; }"
        : "=r"(a) : "l"(p));
    return a;
}

__device__ __forceinline__ void split4(float4 v, uint2& hi, uint2& lo) {
    __nv_bfloat162 h01 = __floats2bfloat162_rn(v.x, v.y);
    __nv_bfloat162 h23 = __floats2bfloat162_rn(v.z, v.w);
    float l0 = v.x - __low2float(h01), l1 = v.y - __high2float(h01);
    float l2 = v.z - __low2float(h23), l3 = v.w - __high2float(h23);
    __nv_bfloat162 lo01 = __floats2bfloat162_rn(l0, l1);
    __nv_bfloat162 lo23 = __floats2bfloat162_rn(l2, l3);
    hi.x = *(uint32_t*)&h01; hi.y = *(uint32_t*)&h23;
    lo.x = *(uint32_t*)&lo01; lo.y = *(uint32_t*)&lo23;
}

__device__ __forceinline__ void mma16816(float* c, const uint32_t* a, const uint32_t* b) {
    asm volatile(
        "mma.sync.aligned.m16n8k16.row.col.f32.bf16.bf16.f32 "
        "{%0,%1,%2,%3},{%4,%5,%6,%7},{%8,%9},{%0,%1,%2,%3};"
        : "+f"(c[0]), "+f"(c[1]), "+f"(c[2]), "+f"(c[3])
        : "r"(a[0]), "r"(a[1]), "r"(a[2]), "r"(a[3]), "r"(b[0]), "r"(b[1]));
}
__device__ __forceinline__ void ldsm4(uint32_t* r, uint32_t addr) {
    asm volatile("ldmatrix.sync.aligned.m8n8.x4.shared.b16 {%0,%1,%2,%3}, [%4];"
                 : "=r"(r[0]), "=r"(r[1]), "=r"(r[2]), "=r"(r[3]) : "r"(addr));
}
__device__ __forceinline__ void cpa16(uint32_t saddr, const void* gaddr) {
    asm volatile("cp.async.cg.shared.global [%0], [%1], 16;" :: "r"(saddr), "l"(gaddr));
}
#define CP_COMMIT() asm volatile("cp.async.commit_group;")
#define CP_WAIT1()  asm volatile("cp.async.wait_group 1;")

// packed f32x2 ops (PTX sm_100+, plain target)
__device__ __forceinline__ ull pk2(float a, float b) {
    ull r; asm("mov.b64 %0, {%1,%2};" : "=l"(r) : "f"(a), "f"(b)); return r;
}
__device__ __forceinline__ void upk2(ull v, float& a, float& b) {
    asm("mov.b64 {%0,%1}, %2;" : "=f"(a), "=f"(b) : "l"(v));
}
__device__ __forceinline__ void fma2(ull& d, ull a, ull b) {     // d += a*b (lanewise)
    asm("fma.rn.f32x2 %0, %1, %2, %0;" : "+l"(d) : "l"(a), "l"(b));
}
__device__ __forceinline__ void mul2(ull& d, ull a) {            // d *= a (via fma + 0)
    asm("fma.rn.f32x2 %0, %0, %1, %2;" : "+l"(d) : "l"(a), "l"(0ULL));
}

// SW128 swizzle for 128B rows: byte = row*128 + (col ^ ((row&7)<<4))
__device__ __forceinline__ uint32_t swz(int row, int col) {
    return (uint32_t)(row * 128 + (col ^ ((row & 7) << 4)));
}

// ===========================================================================
// conversion kernels
// ===========================================================================
__global__ void split_kernel(const float* __restrict__ src,
                             __nv_bfloat16* __restrict__ hi,
                             __nv_bfloat16* __restrict__ lo, int n4) {
    int i = blockIdx.x * blockDim.x + threadIdx.x;
    if (i < n4) {
        float4 v = *(const float4*)(src + (size_t)i * 4);
        uint2 h, l; split4(v, h, l);
        *(uint2*)(hi + (size_t)i * 4) = h;
        *(uint2*)(lo + (size_t)i * 4) = l;
    }
}

// src [K,N] fp32 row-major -> dst [N][K] bf16 hi/lo
__global__ void split_tr_kernel(const float* __restrict__ src,
                                __nv_bfloat16* __restrict__ hi,
                                __nv_bfloat16* __restrict__ lo, int K, int N) {
    __shared__ float t[32][33];
    const int n0 = blockIdx.x * 32, k0 = blockIdx.y * 32;
    const int tx = threadIdx.x, ty = threadIdx.y;   // 32 x 8
#pragma unroll
    for (int i = 0; i < 4; i++)
        t[ty + i * 8][tx] = src[(size_t)(k0 + ty + i * 8) * N + n0 + tx];
    __syncthreads();
#pragma unroll
    for (int i = 0; i < 4; i++) {
        int n = ty + i * 8;
        float v = t[tx][n];
        __nv_bfloat16 h = __float2bfloat16(v);
        float l = v - __bfloat162float(h);
        hi[(size_t)(n0 + n) * K + k0 + tx] = h;
        lo[(size_t)(n0 + n) * K + k0 + tx] = __float2bfloat16(l);
    }
}

// ===========================================================================
// split-precision bf16 GEMM: C[M,N] = Ahl[M,K] @ Bhl[N,K]^T + bias
// CTA 128x128, BK=64, 2-stage cp.async pipeline, SW128 smem, ldmatrix frags.
// ===========================================================================
#define ST_AH 0
#define ST_AL 16384
#define ST_BH 32768
#define ST_BL 49152
#define ST_SZ 65536
#define GSMEM (2 * ST_SZ)

__global__ __launch_bounds__(256, 1)
void gemm_bf16_kernel(const __nv_bfloat16* __restrict__ Ah, const __nv_bfloat16* __restrict__ Al,
                      const __nv_bfloat16* __restrict__ Bh, const __nv_bfloat16* __restrict__ Bl,
                      const float* __restrict__ bias, float* __restrict__ C,
                      int M, int N, int K) {
    extern __shared__ char sm[];
    const uint32_t sb = smem_u32(sm);
    const int tid = threadIdx.x, lane = tid & 31, wid = tid >> 5;
    const int m0 = blockIdx.y * 128, n0 = blockIdx.x * 128;
    const int wm = wid >> 2, wn = wid & 3;          // 2 x 4 warp grid, warp tile 64x32
    const int l15 = lane & 15, chi = (lane >> 4) * 16;

    // cp.async mapping: thread -> (row, 16B chunk)
    const int lrow = tid >> 3;                      // 0..31
    const int lc   = tid & 7;                       // chunk 0..7
    const int NT = K / 64;

    float acc[4][4][4];
#pragma unroll
    for (int i = 0; i < 4; i++)
#pragma unroll
        for (int j = 0; j < 4; j++)
#pragma unroll
            for (int r = 0; r < 4; r++) acc[i][j][r] = 0.f;

    auto load_stage = [&](int s, int kt) {
        const uint32_t sbase = sb + s * ST_SZ;
        const size_t gk = (size_t)kt * 64 + lc * 8;
#pragma unroll
        for (int i = 0; i < 4; i++) {
            const int row = lrow + i * 32;
            const uint32_t so = swz(row, lc * 16);
            cpa16(sbase + ST_AH + so, Ah + (size_t)(m0 + row) * K + gk);
            cpa16(sbase + ST_AL + so, Al + (size_t)(m0 + row) * K + gk);
            cpa16(sbase + ST_BH + so, Bh + (size_t)(n0 + row) * K + gk);
            cpa16(sbase + ST_BL + so, Bl + (size_t)(n0 + row) * K + gk);
        }
    };

    load_stage(0, 0); CP_COMMIT();
    load_stage(1, 1); CP_COMMIT();

    for (int t = 0; t < NT; t++) {
        const int s = t & 1;
        CP_WAIT1();
        __syncthreads();

        const uint32_t abase = sb + s * ST_SZ;
#pragma unroll
        for (int ks = 0; ks < 4; ks++) {
            const int cb = ks * 32 + chi;
            uint32_t Af[4][4], Bf[2][4], Lf[4][4], Mf[2][4];
#pragma unroll
            for (int mt = 0; mt < 4; mt++)
                ldsm4(Af[mt], abase + ST_AH + swz(wm * 64 + mt * 16 + l15, cb));
#pragma unroll
            for (int bt = 0; bt < 2; bt++)
                ldsm4(Bf[bt], abase + ST_BH + swz(wn * 32 + bt * 16 + l15, cb));
            // pass 1: Ah * Bh
#pragma unroll
            for (int mt = 0; mt < 4; mt++)
#pragma unroll
                for (int nt = 0; nt < 4; nt++) {
                    uint32_t b[2] = { Bf[nt >> 1][nt & 1], Bf[nt >> 1][(nt & 1) + 2] };
                    mma16816(acc[mt][nt], Af[mt], b);
                }
            // pass 2: Ah * Bl
#pragma unroll
            for (int bt = 0; bt < 2; bt++)
                ldsm4(Mf[bt], abase + ST_BL + swz(wn * 32 + bt * 16 + l15, cb));
#pragma unroll
            for (int mt = 0; mt < 4; mt++)
#pragma unroll
                for (int nt = 0; nt < 4; nt++) {
                    uint32_t b[2] = { Mf[nt >> 1][nt & 1], Mf[nt >> 1][(nt & 1) + 2] };
                    mma16816(acc[mt][nt], Af[mt], b);
                }
            // pass 3: Al * Bh
#pragma unroll
            for (int mt = 0; mt < 4; mt++)
                ldsm4(Lf[mt], abase + ST_AL + swz(wm * 64 + mt * 16 + l15, cb));
#pragma unroll
            for (int mt = 0; mt < 4; mt++)
#pragma unroll
                for (int nt = 0; nt < 4; nt++) {
                    uint32_t b[2] = { Bf[nt >> 1][nt & 1], Bf[nt >> 1][(nt & 1) + 2] };
                    mma16816(acc[mt][nt], Lf[mt], b);
                }
        }
        __syncthreads();
        if (t + 2 < NT) { load_stage(s, t + 2); CP_COMMIT(); }
    }

    // epilogue
    const int g = lane >> 2, tig = lane & 3;
#pragma unroll
    for (int mt = 0; mt < 4; mt++) {
#pragma unroll
        for (int nt = 0; nt < 4; nt++) {
            int row0 = m0 + wm * 64 + mt * 16 + g;
            int col  = n0 + wn * 32 + nt * 8 + tig * 2;
            float2 bb = *(const float2*)(bias + col);
            float2 v0 = make_float2(acc[mt][nt][0] + bb.x, acc[mt][nt][1] + bb.y);
            float2 v1 = make_float2(acc[mt][nt][2] + bb.x, acc[mt][nt][3] + bb.y);
            *(float2*)(C + (size_t)row0 * N + col)       = v0;
            *(float2*)(C + (size_t)(row0 + 8) * N + col) = v1;
        }
    }
}

// ===========================================================================
// Sliding-window causal attention, packed f32x2 math.
// Writes split bf16 (hi/lo) directly for the proj GEMM.
// ===========================================================================
__global__ __launch_bounds__(64)
void attn_kernel(const float* __restrict__ qkv,
                 __nv_bfloat16* __restrict__ oh, __nv_bfloat16* __restrict__ ol) {
    const int b  = blockIdx.z;
    const int h  = blockIdx.y;
    const int qs = blockIdx.x * 64;
    const int tid = threadIdx.x;
    const int i = qs + tid;

    __shared__ ull ks2[64][32];
    __shared__ ull vs2[64][32];

    const size_t rowStride = 3 * NEMBD;

    const float* qptr = qkv + ((size_t)b * SEQ + i) * rowStride + h * HDIM;
    ull q2[32];
#pragma unroll
    for (int d4 = 0; d4 < 16; d4++)
        *(float4*)&q2[d4 * 2] = *(const float4*)(qptr + d4 * 4);

    ull acc2[32];
#pragma unroll
    for (int d = 0; d < 32; d++) acc2[d] = 0ULL;
    float m = -1e30f, l = 0.f;

    int kt0 = qs - WINDOW;
    if (kt0 < 0) kt0 = 0;

    for (int kt = kt0; kt <= qs; kt += 64) {
        const float* kbase = qkv + ((size_t)b * SEQ + kt) * rowStride + NEMBD + h * HDIM;
        const float* vbase = kbase + NEMBD;
        float* ksf = (float*)&ks2[0][0];
        float* vsf = (float*)&vs2[0][0];
#pragma unroll
        for (int t = 0; t < 16; t++) {
            int idx4 = tid + t * 64;
            int r = idx4 >> 4;
            int c = (idx4 & 15) << 2;
            *(float4*)(ksf + r * 64 + c) = *(const float4*)(kbase + (size_t)r * rowStride + c);
            *(float4*)(vsf + r * 64 + c) = *(const float4*)(vbase + (size_t)r * rowStride + c);
        }
        __syncthreads();

        for (int j = 0; j < 64; j++) {
            const int jg = kt + j;
            // dot product: 4 independent packed partials
            ull s2a = 0ULL, s2b = 0ULL, s2c = 0ULL, s2d = 0ULL;
#pragma unroll
            for (int d = 0; d < 32; d += 4) {
                fma2(s2a, q2[d + 0], ks2[j][d + 0]);
                fma2(s2b, q2[d + 1], ks2[j][d + 1]);
                fma2(s2c, q2[d + 2], ks2[j][d + 2]);
                fma2(s2d, q2[d + 3], ks2[j][d + 3]);
            }
            float xa, xb, xc, xd, ya, yb, yc, yd;
            upk2(s2a, xa, ya); upk2(s2b, xb, yb); upk2(s2c, xc, yc); upk2(s2d, xd, yd);
            float s = ((xa + xb) + (xc + xd)) + ((ya + yb) + (yc + yd));
            s *= ATT_SCALE;
            s = fminf(fmaxf(s, -10000.f), 10000.f);
            const bool valid = (jg <= i) && (jg > i - WINDOW);
            if (valid) {
                if (s > m) {
                    const float corr = __expf(m - s);
                    const ull corr2 = pk2(corr, corr);
                    l *= corr;
#pragma unroll
                    for (int d = 0; d < 32; d++) mul2(acc2[d], corr2);
                    m = s;
                }
                const float p = __expf(s - m);
                l += p;
                const ull p2 = pk2(p, p);
#pragma unroll
                for (int d = 0; d < 32; d++) fma2(acc2[d], p2, vs2[j][d]);
            }
        }
        __syncthreads();
    }

    const float inv = 1.f / l;
    const size_t obase = ((size_t)b * SEQ + i) * NEMBD + h * HDIM;
#pragma unroll
    for (int d = 0; d < 32; d += 2) {
        float a0, a1, a2, a3;
        upk2(acc2[d], a0, a1); upk2(acc2[d + 1], a2, a3);
        float4 o = make_float4(a0 * inv, a1 * inv, a2 * inv, a3 * inv);
        uint2 hv, lv;
        split4(o, hv, lv);
        *(uint2*)(oh + obase + d * 2) = hv;
        *(uint2*)(ol + obase + d * 2) = lv;
    }
}

// ---------------------------------------------------------------------------
extern "C" void kernel_launch(void* const* d_in, const int* in_sizes, int n_in,
                              void* d_out, int out_size) {
    const float* hidden = (const float*)d_in[0];  // [B, T, E]
    const float* w_attn = (const float*)d_in[1];  // [E, 3E]
    const float* b_attn = (const float*)d_in[2];  // [3E]
    const float* w_proj = (const float*)d_in[3];  // [E, E]
    const float* b_proj = (const float*)d_in[4];  // [E]
    float* out = (float*)d_out;

    float* qkv; cudaGetSymbolAddress((void**)&qkv, g_qkv);
    __nv_bfloat16 *ah, *al, *wh, *wl, *ph, *pl, *oh, *ol;
    cudaGetSymbolAddress((void**)&ah, g_ah); cudaGetSymbolAddress((void**)&al, g_al);
    cudaGetSymbolAddress((void**)&wh, g_wh); cudaGetSymbolAddress((void**)&wl, g_wl);
    cudaGetSymbolAddress((void**)&ph, g_ph); cudaGetSymbolAddress((void**)&pl, g_pl);
    cudaGetSymbolAddress((void**)&oh, g_oh); cudaGetSymbolAddress((void**)&ol, g_ol);

    const int M = BATCH * SEQ;       // 4096
    const int E = NEMBD;             // 1024

    cudaFuncSetAttribute(gemm_bf16_kernel,
                         cudaFuncAttributeMaxDynamicSharedMemorySize, GSMEM);

    // 0a) split hidden -> bf16 hi/lo
    {
        int n4 = M * E / 4;
        split_kernel<<<(n4 + 255) / 256, 256>>>(hidden, ah, al, n4);
    }
    // 0b) split+transpose weights
    split_tr_kernel<<<dim3(3 * E / 32, E / 32), dim3(32, 8)>>>(w_attn, wh, wl, E, 3 * E);
    split_tr_kernel<<<dim3(E / 32, E / 32), dim3(32, 8)>>>(w_proj, ph, pl, E, E);

    // 1) QKV projection
    gemm_bf16_kernel<<<dim3(3 * E / 128, M / 128), 256, GSMEM>>>(
        ah, al, wh, wl, b_attn, qkv, M, 3 * E, E);
    // 2) windowed attention (writes split bf16)
    attn_kernel<<<dim3(SEQ / 64, NHEAD, BATCH), 64>>>(qkv, oh, ol);
    // 3) output projection
    gemm_bf16_kernel<<<dim3(E / 128, M / 128), 256, GSMEM>>>(
        oh, ol, ph, pl, b_proj, out, M, E, E);
}